// round 3
// baseline (speedup 1.0000x reference)
#include <cuda_runtime.h>
#include <math.h>

#define BB 2048
#define TT 7
#define NNODE 90
#define FD 27
#define HD 30
#define NF 2430      // NNODE*FD
#define TNF 17010    // TT*NF
#define NH 2700      // NNODE*HD

// ---------------- scratch (static device globals; no allocation) ----------------
__device__ __align__(256) float g_xt[BB * TNF];      // x_tat, [b][t][n][f]
__device__ __align__(256) float g_conf[BB * TT];
__device__ __align__(256) float g_final[BB * NH];
__device__ __align__(256) float g_h1[BB * 1024];
__device__ __align__(256) float g_h2[BB * 256];
__device__ __align__(256) float g_gacc[32];
__device__ __align__(256) float g_gl[32];
__device__ __align__(256) float g_bnA1[1024];
__device__ __align__(256) float g_bnB1[1024];
__device__ __align__(256) float g_bnA2[256];
__device__ __align__(256) float g_bnB2[256];

// ---------------- attention + x_tat (one block per batch element) ----------------
#define ATTN_SMEM_BYTES (21251 * 4)

__global__ __launch_bounds__(256) void attn_kernel(
    const float* __restrict__ fdata, const float* __restrict__ U1,
    const float* __restrict__ U2, const float* __restrict__ U3,
    const float* __restrict__ be, const float* __restrict__ ve,
    float* __restrict__ xt)
{
    extern __shared__ float sm[];
    float* sfd  = sm;           // 17010
    float* sU1  = sm + 17010;   // 90
    float* sU2  = sm + 17100;   // 2430
    float* sU3  = sm + 19530;   // 27
    float* sbe  = sm + 19557;   // 49
    float* sve  = sm + 19606;   // 49
    float* slA  = sm + 19655;   // 189
    float* slhs = sm + 19844;   // 630
    float* srhs = sm + 20474;   // 630
    float* sp   = sm + 21104;   // 49
    float* ss   = sm + 21153;   // 49
    float* stt  = sm + 21202;   // 49

    int b = blockIdx.x, tid = threadIdx.x;
    const float* src = fdata + (size_t)b * TNF;
    for (int i = tid; i < TNF; i += 256) sfd[i] = src[i];
    for (int i = tid; i < 90; i += 256) sU1[i] = U1[i];
    for (int i = tid; i < 2430; i += 256) sU2[i] = U2[i];
    if (tid < 27) sU3[tid] = U3[tid];
    if (tid < 49) { sbe[tid] = be[tid]; sve[tid] = ve[tid]; }
    __syncthreads();

    // lhsA[t][f] = sum_v fd[t,v,f]*U1[v];  rhs[v][t] = sum_f fd[t,v,f]*U3[f]
    for (int o = tid; o < 189; o += 256) {
        int t = o / 27, f = o % 27;
        float a = 0.f;
        for (int v = 0; v < NNODE; v++) a += sfd[t * NF + v * 27 + f] * sU1[v];
        slA[o] = a;
    }
    for (int o = tid; o < 630; o += 256) {
        int v = o / 7, t = o % 7;
        float a = 0.f;
        for (int f = 0; f < 27; f++) a += sfd[t * NF + v * 27 + f] * sU3[f];
        srhs[v * 7 + t] = a;
    }
    __syncthreads();

    // lhs[t][n] = sum_f lhsA[t][f]*U2[f][n]
    for (int o = tid; o < 630; o += 256) {
        int t = o / 90, n = o % 90;
        float a = 0.f;
        for (int f = 0; f < 27; f++) a += slA[t * 27 + f] * sU2[f * 90 + n];
        slhs[o] = a;
    }
    __syncthreads();

    // p[t][s] = sigmoid(sum_v lhs[t][v]*rhs[v][s] + be[t][s])
    if (tid < 49) {
        int t = tid / 7, s = tid % 7;
        float a = 0.f;
        for (int v = 0; v < 90; v++) a += slhs[t * 90 + v] * srhs[v * 7 + s];
        sp[tid] = 1.f / (1.f + expf(-(a + sbe[tid])));
    }
    __syncthreads();

    // ss[k][i] = sum_j ve[i][j]*p[k][j]
    if (tid < 49) {
        int k = tid / 7, i = tid % 7;
        float a = 0.f;
        for (int j = 0; j < 7; j++) a += sve[i * 7 + j] * sp[k * 7 + j];
        ss[tid] = a;
    }
    __syncthreads();

    // tatt = softmax over k (axis 1) for each column i
    if (tid < 7) {
        int i = tid;
        float mx = -1e30f;
        for (int k = 0; k < 7; k++) mx = fmaxf(mx, ss[k * 7 + i]);
        float ex[7], sum = 0.f;
        for (int k = 0; k < 7; k++) { ex[k] = expf(ss[k * 7 + i] - mx); sum += ex[k]; }
        float inv = 1.f / sum;
        for (int k = 0; k < 7; k++) stt[k * 7 + i] = ex[k] * inv;
    }
    __syncthreads();

    // x_tat flat element o: i = o/7, j = o%7 ; out = sum_s fd_flat[s*NF+i]*tatt[s][j]
    float* dst = xt + (size_t)b * TNF;
    for (int o = tid; o < TNF; o += 256) {
        int i = o / 7, j = o % 7;
        float a = 0.f;
        #pragma unroll
        for (int s = 0; s < 7; s++) a += sfd[s * NF + i] * stt[s * 7 + j];
        dst[o] = a;
    }
}

// ---------------- confidence (replicates the raw (T*B,NF) reshape quirk) ----------------
__global__ __launch_bounds__(256) void conf_kernel(
    const float* __restrict__ fdata, const float* __restrict__ unw,
    const float* __restrict__ unb, float* __restrict__ conf)
{
    int gw = (blockIdx.x * blockDim.x + threadIdx.x) >> 5;
    int lane = threadIdx.x & 31;
    if (gw >= BB * TT) return;
    // output flat idx gw = b*7+t reads x_t row gw: tsrc = gw/B, bsrc = gw%B
    int bsrc = gw % BB, tsrc = gw / BB;
    const float* v = fdata + ((size_t)bsrc * TT + tsrc) * NF;
    float a = 0.f;
    for (int k = lane; k < NF; k += 32) a += v[k] * unw[k];
    #pragma unroll
    for (int off = 16; off > 0; off >>= 1) a += __shfl_down_sync(0xffffffffu, a, off);
    if (lane == 0) conf[gw] = 1.f / (1.f + expf(-(a + unb[0])));
}

// ---------------- gl recurrence helpers ----------------
__global__ void init_kernel(const float* __restrict__ linb,
                            float* __restrict__ gl, float* __restrict__ gacc)
{
    int tid = threadIdx.x;
    if (tid < 27) gl[tid] = linb[tid];   // gm = 0 at step 0
    if (tid < 30) gacc[tid] = 0.f;
}

__global__ void gl_kernel(const float* __restrict__ linw, const float* __restrict__ linb,
                          float* __restrict__ gl, float* __restrict__ gacc)
{
    __shared__ float gm[30];
    int tid = threadIdx.x;
    if (tid < 30) { gm[tid] = gacc[tid] * (1.0f / (float)(BB * NNODE)); gacc[tid] = 0.f; }
    __syncthreads();
    if (tid < 27) {
        float a = linb[tid];
        for (int h = 0; h < 30; h++) a += linw[tid * 30 + h] * gm[h];
        gl[tid] = a;
    }
}

// ---------------- ST block ----------------
// Y[90][30] = A[90][K] (row stride LDA) @ Bm[K][30], 3x3 register tiles
template <int K, int LDA>
__device__ __forceinline__ void mm_30(const float* __restrict__ A, const float* __restrict__ Bm,
                                      float* __restrict__ Y, int tid, int NT)
{
    for (int g = tid; g < 300; g += NT) {
        int n0 = (g / 10) * 3, h0 = (g % 10) * 3;
        float acc[3][3];
        #pragma unroll
        for (int r = 0; r < 3; r++)
            #pragma unroll
            for (int c = 0; c < 3; c++) acc[r][c] = 0.f;
        for (int k = 0; k < K; k++) {
            float b0 = Bm[k * 30 + h0], b1 = Bm[k * 30 + h0 + 1], b2 = Bm[k * 30 + h0 + 2];
            float a0 = A[n0 * LDA + k], a1 = A[(n0 + 1) * LDA + k], a2 = A[(n0 + 2) * LDA + k];
            acc[0][0] += a0 * b0; acc[0][1] += a0 * b1; acc[0][2] += a0 * b2;
            acc[1][0] += a1 * b0; acc[1][1] += a1 * b1; acc[1][2] += a1 * b2;
            acc[2][0] += a2 * b0; acc[2][1] += a2 * b1; acc[2][2] += a2 * b2;
        }
        #pragma unroll
        for (int r = 0; r < 3; r++)
            #pragma unroll
            for (int c = 0; c < 3; c++) Y[(n0 + r) * 30 + h0 + c] = acc[r][c];
    }
}

#define ST_SMEM_BYTES (44577 * 4)

__global__ __launch_bounds__(512, 1) void st_kernel(
    const float* __restrict__ xt, const float* __restrict__ w,
    const float* __restrict__ cb, const float* __restrict__ gc1,
    const float* __restrict__ gc2, const float* __restrict__ conf,
    const float* __restrict__ gl, float* __restrict__ fin,
    float* __restrict__ gacc, int t)
{
    extern __shared__ float sm[];
    float* sf   = sm;           // 2430  f
    float* sxc  = sm + 2430;    // 2430  centered
    float* sadj = sm + 4860;    // 8100
    float* sA   = sm + 12960;   // 2700 ping
    float* sB   = sm + 15660;   // 2700 pong
    float* sw   = sm + 18360;   // 24300 conv weights
    float* sgc1 = sm + 42660;   // 810
    float* sgc2 = sm + 43470;   // 900
    float* sd   = sm + 44370;   // 90
    float* sgl  = sm + 44460;   // 27
    float* scb  = sm + 44487;   // 90

    int b = blockIdx.x, tid = threadIdx.x;
    const int NT = 512;
    const float* src = xt + (size_t)b * TNF + (size_t)t * NF;
    for (int i = tid; i < NF; i += NT) sf[i] = src[i];
    for (int i = tid; i < 24300; i += NT) sw[i] = w[i];
    for (int i = tid; i < 810; i += NT) sgc1[i] = gc1[i];
    for (int i = tid; i < 900; i += NT) sgc2[i] = gc2[i];
    if (tid < 90) scb[tid] = cb[tid];
    else if (tid >= 128 && tid < 155) sgl[tid - 128] = gl[tid - 128];
    __syncthreads();

    // row means -> centered copy
    if (tid < 90) {
        float s = 0.f;
        for (int f = 0; f < 27; f++) s += sf[tid * 27 + f];
        sd[tid] = s * (1.f / 27.f);
    }
    __syncthreads();
    for (int i = tid; i < NF; i += NT) sxc[i] = sf[i] - sd[i / 27];
    __syncthreads();

    // cov = xc xc^T (3x3 tiles)
    for (int g = tid; g < 900; g += NT) {
        int n0 = (g / 30) * 3, m0 = (g % 30) * 3;
        float acc[3][3];
        #pragma unroll
        for (int r = 0; r < 3; r++)
            #pragma unroll
            for (int c = 0; c < 3; c++) acc[r][c] = 0.f;
        for (int f = 0; f < 27; f++) {
            float a0 = sxc[n0 * 27 + f], a1 = sxc[(n0 + 1) * 27 + f], a2 = sxc[(n0 + 2) * 27 + f];
            float c0 = sxc[m0 * 27 + f], c1 = sxc[(m0 + 1) * 27 + f], c2 = sxc[(m0 + 2) * 27 + f];
            acc[0][0] += a0 * c0; acc[0][1] += a0 * c1; acc[0][2] += a0 * c2;
            acc[1][0] += a1 * c0; acc[1][1] += a1 * c1; acc[1][2] += a1 * c2;
            acc[2][0] += a2 * c0; acc[2][1] += a2 * c1; acc[2][2] += a2 * c2;
        }
        #pragma unroll
        for (int r = 0; r < 3; r++)
            #pragma unroll
            for (int c = 0; c < 3; c++) sadj[(n0 + r) * 90 + m0 + c] = acc[r][c];
    }
    __syncthreads();
    if (tid < 90) sd[tid] = rsqrtf(sadj[tid * 91]);
    __syncthreads();
    for (int i = tid; i < 8100; i += NT) sadj[i] *= sd[i / 90] * sd[i % 90];
    __syncthreads();

    // conv1: l = conv1x3(f) + cb + gl  (2-row x 4-col tiles, 45*7 groups)
    for (int g = tid; g < 315; g += NT) {
        int n0 = (g / 7) * 2, x0 = (g % 7) * 4;
        float acc[2][4];
        #pragma unroll
        for (int r = 0; r < 2; r++)
            #pragma unroll
            for (int xi = 0; xi < 4; xi++) acc[r][xi] = 0.f;
        for (int i = 0; i < 90; i++) {
            float fv[6];
            #pragma unroll
            for (int q = 0; q < 6; q++) {
                int xx = x0 - 1 + q;
                fv[q] = (xx >= 0 && xx < 27) ? sf[i * 27 + xx] : 0.f;
            }
            #pragma unroll
            for (int r = 0; r < 2; r++) {
                const float* wp = sw + ((n0 + r) * 90 + i) * 3;
                float w0 = wp[0], w1 = wp[1], w2 = wp[2];
                #pragma unroll
                for (int xi = 0; xi < 4; xi++)
                    acc[r][xi] += w0 * fv[xi] + w1 * fv[xi + 1] + w2 * fv[xi + 2];
            }
        }
        #pragma unroll
        for (int r = 0; r < 2; r++)
            #pragma unroll
            for (int xi = 0; xi < 4; xi++) {
                int x = x0 + xi;
                if (x < 27) sA[(n0 + r) * 27 + x] = acc[r][xi] + scb[n0 + r] + sgl[x];
            }
    }
    __syncthreads();

    mm_30<27, 27>(sA, sgc1, sB, tid, NT);   // t1 = l @ gc1
    __syncthreads();
    mm_30<90, 90>(sadj, sB, sA, tid, NT);   // s1 = adj @ t1
    __syncthreads();
    mm_30<30, 30>(sA, sgc2, sB, tid, NT);   // t2 = s1 @ gc2
    __syncthreads();
    mm_30<90, 90>(sadj, sB, sA, tid, NT);   // g_out = adj @ t2  -> sA
    __syncthreads();

    // accumulate global column sums of g_out
    if (tid < 30) {
        float s = 0.f;
        for (int n = 0; n < 90; n++) s += sA[n * 30 + tid];
        atomicAdd(&gacc[tid], s);
    }

    float cf = conf[b * TT + t];
    // conv2 on g_out (L=30): 2-row x 5-col tiles, fused conf-weighted accumulate
    for (int g = tid; g < 270; g += NT) {
        int n0 = (g / 6) * 2, x0 = (g % 6) * 5;
        float acc[2][5];
        #pragma unroll
        for (int r = 0; r < 2; r++)
            #pragma unroll
            for (int xi = 0; xi < 5; xi++) acc[r][xi] = 0.f;
        for (int i = 0; i < 90; i++) {
            float fv[7];
            #pragma unroll
            for (int q = 0; q < 7; q++) {
                int xx = x0 - 1 + q;
                fv[q] = (xx >= 0 && xx < 30) ? sA[i * 30 + xx] : 0.f;
            }
            #pragma unroll
            for (int r = 0; r < 2; r++) {
                const float* wp = sw + ((n0 + r) * 90 + i) * 3;
                float w0 = wp[0], w1 = wp[1], w2 = wp[2];
                #pragma unroll
                for (int xi = 0; xi < 5; xi++)
                    acc[r][xi] += w0 * fv[xi] + w1 * fv[xi + 1] + w2 * fv[xi + 2];
            }
        }
        #pragma unroll
        for (int r = 0; r < 2; r++)
            #pragma unroll
            for (int xi = 0; xi < 5; xi++) {
                int idx = b * NH + (n0 + r) * 30 + x0 + xi;
                float val = (acc[r][xi] + scb[n0 + r]) * cf;
                if (t == 0) fin[idx] = val;
                else        fin[idx] += val;
            }
    }
}

// ---------------- head GEMM: C[M,N] = (A*bnA+bnB)[M,K] @ W[N,K]^T + bias ----------------
__global__ __launch_bounds__(256) void gemm_kernel(
    const float* __restrict__ A, const float* __restrict__ W,
    const float* __restrict__ bias, const float* __restrict__ bnA,
    const float* __restrict__ bnB, float* __restrict__ C,
    int M, int N, int K)
{
    __shared__ float As[16][68];
    __shared__ float Ws[16][68];
    int m0 = blockIdx.y * 64, n0 = blockIdx.x * 64;
    int tid = threadIdx.x;
    int lr = tid >> 2;          // 0..63
    int lk = (tid & 3) * 4;     // 0,4,8,12
    int tx = tid & 15, ty = tid >> 4;
    float acc[4][4];
    #pragma unroll
    for (int i = 0; i < 4; i++)
        #pragma unroll
        for (int j = 0; j < 4; j++) acc[i][j] = 0.f;

    int ktiles = (K + 15) / 16;
    for (int kt = 0; kt < ktiles; kt++) {
        int k0 = kt * 16;
        float4 av, wv;
        if (k0 + lk < K) {  // K % 4 == 0, lk % 4 == 0 -> full float4 valid
            av = *(const float4*)(A + (size_t)(m0 + lr) * K + k0 + lk);
            if (bnA) {
                float4 sA4 = *(const float4*)(bnA + k0 + lk);
                float4 sB4 = *(const float4*)(bnB + k0 + lk);
                av.x = av.x * sA4.x + sB4.x; av.y = av.y * sA4.y + sB4.y;
                av.z = av.z * sA4.z + sB4.z; av.w = av.w * sA4.w + sB4.w;
            }
            wv = *(const float4*)(W + (size_t)(n0 + lr) * K + k0 + lk);
        } else {
            av = make_float4(0.f, 0.f, 0.f, 0.f);
            wv = make_float4(0.f, 0.f, 0.f, 0.f);
        }
        __syncthreads();
        As[lk][lr] = av.x; As[lk + 1][lr] = av.y; As[lk + 2][lr] = av.z; As[lk + 3][lr] = av.w;
        Ws[lk][lr] = wv.x; Ws[lk + 1][lr] = wv.y; Ws[lk + 2][lr] = wv.z; Ws[lk + 3][lr] = wv.w;
        __syncthreads();
        #pragma unroll
        for (int kk = 0; kk < 16; kk++) {
            float rA[4], rB[4];
            #pragma unroll
            for (int i = 0; i < 4; i++) rA[i] = As[kk][ty * 4 + i];
            #pragma unroll
            for (int j = 0; j < 4; j++) rB[j] = Ws[kk][tx * 4 + j];
            #pragma unroll
            for (int i = 0; i < 4; i++)
                #pragma unroll
                for (int j = 0; j < 4; j++) acc[i][j] += rA[i] * rB[j];
        }
    }
    #pragma unroll
    for (int i = 0; i < 4; i++) {
        int m = m0 + ty * 4 + i;
        #pragma unroll
        for (int j = 0; j < 4; j++) {
            int n = n0 + tx * 4 + j;
            C[(size_t)m * N + n] = acc[i][j] + bias[n];
        }
    }
}

// ---------------- BN stats: per-column mean/var -> affine (bnA, bnB) ----------------
__global__ void bnstats_kernel(const float* __restrict__ C,
                               const float* __restrict__ gamma, const float* __restrict__ beta,
                               float* __restrict__ bnA, float* __restrict__ bnB, int N)
{
    __shared__ double rs[8][32];
    __shared__ double rq[8][32];
    int col = blockIdx.x * 32 + threadIdx.x;
    int g = threadIdx.y;
    double s = 0.0, q = 0.0;
    for (int r = g; r < BB; r += 8) {
        double v = (double)C[(size_t)r * N + col];
        s += v; q += v * v;
    }
    rs[g][threadIdx.x] = s; rq[g][threadIdx.x] = q;
    __syncthreads();
    if (g == 0) {
        for (int k = 1; k < 8; k++) { s += rs[k][threadIdx.x]; q += rq[k][threadIdx.x]; }
        float mean = (float)(s / (double)BB);
        float var = (float)(q / (double)BB) - mean * mean;
        float a = gamma[col] * rsqrtf(var + 1e-5f);
        bnA[col] = a;
        bnB[col] = beta[col] - mean * a;
    }
}

// ---------------- final: bn2-apply + 256->2 linear + softmax ----------------
__global__ __launch_bounds__(256) void head_kernel(
    const float* __restrict__ h2, const float* __restrict__ bnA,
    const float* __restrict__ bnB, const float* __restrict__ l3w,
    const float* __restrict__ l3b, float* __restrict__ out)
{
    int gw = (blockIdx.x * blockDim.x + threadIdx.x) >> 5;
    int lane = threadIdx.x & 31;
    if (gw >= BB) return;
    const float* row = h2 + (size_t)gw * 256;
    float z0 = 0.f, z1 = 0.f;
    for (int k = lane; k < 256; k += 32) {
        float hb = row[k] * bnA[k] + bnB[k];
        z0 += hb * l3w[k];
        z1 += hb * l3w[256 + k];
    }
    #pragma unroll
    for (int off = 16; off > 0; off >>= 1) {
        z0 += __shfl_down_sync(0xffffffffu, z0, off);
        z1 += __shfl_down_sync(0xffffffffu, z1, off);
    }
    if (lane == 0) {
        z0 += l3b[0]; z1 += l3b[1];
        float m = fmaxf(z0, z1);
        float e0 = expf(z0 - m), e1 = expf(z1 - m);
        float inv = 1.f / (e0 + e1);
        out[gw * 2 + 0] = e0 * inv;
        out[gw * 2 + 1] = e1 * inv;
    }
}

// ---------------- launch ----------------
extern "C" void kernel_launch(void* const* d_in, const int* in_sizes, int n_in,
                              void* d_out, int out_size)
{
    const float* fdata = (const float*)d_in[0];
    const float* un_w  = (const float*)d_in[1];
    const float* un_b  = (const float*)d_in[2];
    const float* U1    = (const float*)d_in[3];
    const float* U2    = (const float*)d_in[4];
    const float* U3    = (const float*)d_in[5];
    const float* b_e   = (const float*)d_in[6];
    const float* v_e   = (const float*)d_in[7];
    const float* gc1_w = (const float*)d_in[8];
    const float* gc2_w = (const float*)d_in[9];
    const float* cnn1w = (const float*)d_in[10];
    const float* cnn1b = (const float*)d_in[11];
    const float* lin_w = (const float*)d_in[12];
    const float* lin_b = (const float*)d_in[13];
    const float* l1_w  = (const float*)d_in[14];
    const float* l1_b  = (const float*)d_in[15];
    const float* bn1_g = (const float*)d_in[16];
    const float* bn1_b = (const float*)d_in[17];
    const float* l2_w  = (const float*)d_in[18];
    const float* l2_b  = (const float*)d_in[19];
    const float* bn2_g = (const float*)d_in[20];
    const float* bn2_b = (const float*)d_in[21];
    const float* l3_w  = (const float*)d_in[22];
    const float* l3_b  = (const float*)d_in[23];
    float* out = (float*)d_out;

    // Host-side attribute set: non-stream API, no static guard (determinism rule).
    cudaFuncSetAttribute(attn_kernel, cudaFuncAttributeMaxDynamicSharedMemorySize, ATTN_SMEM_BYTES);
    cudaFuncSetAttribute(st_kernel, cudaFuncAttributeMaxDynamicSharedMemorySize, ST_SMEM_BYTES);

    float *xt, *conf, *fin, *h1, *h2, *gacc, *gl, *bnA1, *bnB1, *bnA2, *bnB2;
    cudaGetSymbolAddress((void**)&xt, g_xt);
    cudaGetSymbolAddress((void**)&conf, g_conf);
    cudaGetSymbolAddress((void**)&fin, g_final);
    cudaGetSymbolAddress((void**)&h1, g_h1);
    cudaGetSymbolAddress((void**)&h2, g_h2);
    cudaGetSymbolAddress((void**)&gacc, g_gacc);
    cudaGetSymbolAddress((void**)&gl, g_gl);
    cudaGetSymbolAddress((void**)&bnA1, g_bnA1);
    cudaGetSymbolAddress((void**)&bnB1, g_bnB1);
    cudaGetSymbolAddress((void**)&bnA2, g_bnA2);
    cudaGetSymbolAddress((void**)&bnB2, g_bnB2);

    attn_kernel<<<BB, 256, ATTN_SMEM_BYTES>>>(fdata, U1, U2, U3, b_e, v_e, xt);
    conf_kernel<<<(BB * TT * 32 + 255) / 256, 256>>>(fdata, un_w, un_b, conf);
    init_kernel<<<1, 32>>>(lin_b, gl, gacc);
    for (int t = 0; t < TT; t++) {
        st_kernel<<<BB, 512, ST_SMEM_BYTES>>>(xt, cnn1w, cnn1b, gc1_w, gc2_w, conf, gl, fin, gacc, t);
        if (t < TT - 1)
            gl_kernel<<<1, 32>>>(lin_w, lin_b, gl, gacc);
    }
    gemm_kernel<<<dim3(1024 / 64, BB / 64), 256>>>(fin, l1_w, l1_b, nullptr, nullptr, h1, BB, 1024, NH);
    bnstats_kernel<<<1024 / 32, dim3(32, 8)>>>(h1, bn1_g, bn1_b, bnA1, bnB1, 1024);
    gemm_kernel<<<dim3(256 / 64, BB / 64), 256>>>(h1, l2_w, l2_b, bnA1, bnB1, h2, BB, 256, 1024);
    bnstats_kernel<<<256 / 32, dim3(32, 8)>>>(h2, bn2_g, bn2_b, bnA2, bnB2, 256);
    head_kernel<<<(BB * 32 + 255) / 256, 256>>>(h2, bnA2, bnB2, l3_w, l3_b, out);
}

// round 4
// speedup vs baseline: 1.1743x; 1.1743x over previous
#include <cuda_runtime.h>
#include <math.h>

#define BB 2048
#define TT 7
#define NNODE 90
#define FD 27
#define HD 30
#define NF 2430      // NNODE*FD
#define TNF 17010    // TT*NF
#define NH 2700      // NNODE*HD

// ---------------- scratch (static device globals; no allocation) ----------------
__device__ __align__(256) float g_xt[BB * TNF];      // x_tat, [b][t][n][f]
__device__ __align__(256) float g_conf[BB * TT];
__device__ __align__(256) float g_final[BB * NH];
__device__ __align__(256) float g_h1[BB * 1024];
__device__ __align__(256) float g_h2[BB * 256];
__device__ __align__(256) float g_gacc[32];
__device__ __align__(256) float g_gl[32];
__device__ __align__(256) float g_bnA1[1024];
__device__ __align__(256) float g_bnB1[1024];
__device__ __align__(256) float g_bnA2[256];
__device__ __align__(256) float g_bnB2[256];

// ---------------- attention + x_tat (one block per batch element) ----------------
#define ATTN_SMEM_BYTES (21251 * 4)

__global__ __launch_bounds__(256) void attn_kernel(
    const float* __restrict__ fdata, const float* __restrict__ U1,
    const float* __restrict__ U2, const float* __restrict__ U3,
    const float* __restrict__ be, const float* __restrict__ ve,
    float* __restrict__ xt)
{
    extern __shared__ float sm[];
    float* sfd  = sm;           // 17010
    float* sU1  = sm + 17010;   // 90
    float* sU2  = sm + 17100;   // 2430
    float* sU3  = sm + 19530;   // 27
    float* sbe  = sm + 19557;   // 49
    float* sve  = sm + 19606;   // 49
    float* slA  = sm + 19655;   // 189
    float* slhs = sm + 19844;   // 630
    float* srhs = sm + 20474;   // 630
    float* sp   = sm + 21104;   // 49
    float* ss   = sm + 21153;   // 49
    float* stt  = sm + 21202;   // 49

    int b = blockIdx.x, tid = threadIdx.x;
    const float* src = fdata + (size_t)b * TNF;
    for (int i = tid; i < TNF; i += 256) sfd[i] = src[i];
    for (int i = tid; i < 90; i += 256) sU1[i] = U1[i];
    for (int i = tid; i < 2430; i += 256) sU2[i] = U2[i];
    if (tid < 27) sU3[tid] = U3[tid];
    if (tid < 49) { sbe[tid] = be[tid]; sve[tid] = ve[tid]; }
    __syncthreads();

    for (int o = tid; o < 189; o += 256) {
        int t = o / 27, f = o % 27;
        float a = 0.f;
        for (int v = 0; v < NNODE; v++) a += sfd[t * NF + v * 27 + f] * sU1[v];
        slA[o] = a;
    }
    for (int o = tid; o < 630; o += 256) {
        int v = o / 7, t = o % 7;
        float a = 0.f;
        for (int f = 0; f < 27; f++) a += sfd[t * NF + v * 27 + f] * sU3[f];
        srhs[v * 7 + t] = a;
    }
    __syncthreads();

    for (int o = tid; o < 630; o += 256) {
        int t = o / 90, n = o % 90;
        float a = 0.f;
        for (int f = 0; f < 27; f++) a += slA[t * 27 + f] * sU2[f * 90 + n];
        slhs[o] = a;
    }
    __syncthreads();

    if (tid < 49) {
        int t = tid / 7, s = tid % 7;
        float a = 0.f;
        for (int v = 0; v < 90; v++) a += slhs[t * 90 + v] * srhs[v * 7 + s];
        sp[tid] = 1.f / (1.f + expf(-(a + sbe[tid])));
    }
    __syncthreads();

    if (tid < 49) {
        int k = tid / 7, i = tid % 7;
        float a = 0.f;
        for (int j = 0; j < 7; j++) a += sve[i * 7 + j] * sp[k * 7 + j];
        ss[tid] = a;
    }
    __syncthreads();

    if (tid < 7) {
        int i = tid;
        float mx = -1e30f;
        for (int k = 0; k < 7; k++) mx = fmaxf(mx, ss[k * 7 + i]);
        float ex[7], sum = 0.f;
        for (int k = 0; k < 7; k++) { ex[k] = expf(ss[k * 7 + i] - mx); sum += ex[k]; }
        float inv = 1.f / sum;
        for (int k = 0; k < 7; k++) stt[k * 7 + i] = ex[k] * inv;
    }
    __syncthreads();

    float* dst = xt + (size_t)b * TNF;
    for (int o = tid; o < TNF; o += 256) {
        int i = o / 7, j = o % 7;
        float a = 0.f;
        #pragma unroll
        for (int s = 0; s < 7; s++) a += sfd[s * NF + i] * stt[s * 7 + j];
        dst[o] = a;
    }
}

// ---------------- confidence (replicates the raw (T*B,NF) reshape quirk) ----------------
__global__ __launch_bounds__(256) void conf_kernel(
    const float* __restrict__ fdata, const float* __restrict__ unw,
    const float* __restrict__ unb, float* __restrict__ conf)
{
    int gw = (blockIdx.x * blockDim.x + threadIdx.x) >> 5;
    int lane = threadIdx.x & 31;
    if (gw >= BB * TT) return;
    int bsrc = gw % BB, tsrc = gw / BB;
    const float* v = fdata + ((size_t)bsrc * TT + tsrc) * NF;
    float a = 0.f;
    for (int k = lane; k < NF; k += 32) a += v[k] * unw[k];
    #pragma unroll
    for (int off = 16; off > 0; off >>= 1) a += __shfl_down_sync(0xffffffffu, a, off);
    if (lane == 0) conf[gw] = 1.f / (1.f + expf(-(a + unb[0])));
}

// ---------------- gl recurrence helpers ----------------
__global__ void init_kernel(const float* __restrict__ linb,
                            float* __restrict__ gl, float* __restrict__ gacc)
{
    int tid = threadIdx.x;
    if (tid < 27) gl[tid] = linb[tid];
    if (tid < 30) gacc[tid] = 0.f;
}

__global__ void gl_kernel(const float* __restrict__ linw, const float* __restrict__ linb,
                          float* __restrict__ gl, float* __restrict__ gacc)
{
    __shared__ float gm[30];
    int tid = threadIdx.x;
    if (tid < 30) { gm[tid] = gacc[tid] * (1.0f / (float)(BB * NNODE)); gacc[tid] = 0.f; }
    __syncthreads();
    if (tid < 27) {
        float a = linb[tid];
        for (int h = 0; h < 30; h++) a += linw[tid * 30 + h] * gm[h];
        gl[tid] = a;
    }
}

// ---------------- ST block ----------------
// Y[90][30] = A[90][K] (row stride LDA) @ Bm[K][30], 3x3 register tiles
template <int K, int LDA>
__device__ __forceinline__ void mm_30(const float* __restrict__ A, const float* __restrict__ Bm,
                                      float* __restrict__ Y, int tid, int NT)
{
    for (int g = tid; g < 300; g += NT) {
        int n0 = (g / 10) * 3, h0 = (g % 10) * 3;
        float acc[3][3];
        #pragma unroll
        for (int r = 0; r < 3; r++)
            #pragma unroll
            for (int c = 0; c < 3; c++) acc[r][c] = 0.f;
        for (int k = 0; k < K; k++) {
            float b0 = Bm[k * 30 + h0], b1 = Bm[k * 30 + h0 + 1], b2 = Bm[k * 30 + h0 + 2];
            float a0 = A[n0 * LDA + k], a1 = A[(n0 + 1) * LDA + k], a2 = A[(n0 + 2) * LDA + k];
            acc[0][0] += a0 * b0; acc[0][1] += a0 * b1; acc[0][2] += a0 * b2;
            acc[1][0] += a1 * b0; acc[1][1] += a1 * b1; acc[1][2] += a1 * b2;
            acc[2][0] += a2 * b0; acc[2][1] += a2 * b1; acc[2][2] += a2 * b2;
        }
        #pragma unroll
        for (int r = 0; r < 3; r++)
            #pragma unroll
            for (int c = 0; c < 3; c++) Y[(n0 + r) * 30 + h0 + c] = acc[r][c];
    }
}

// smem layout (floats):
//  [0      : 2432 )  sf (2430); after cov dies -> gc1 (810) @ +0, gc2 (900) @ +810
//  [2432   : 15936)  U region (13504): {w_half <=12420} union {adj 8100 | sA @+8100 | sB @+10800}
//  [15936  : 18640)  G region (2704): l (conv1 out, stride 27) then g_out (mm4 out, stride 30)
//  [18640  : 18736)  sd   (90)  means, then rsqrt(diag)
//  [18736  : 18832)  scb  (90)
//  [18832  : 18864)  sgl  (27)
#define ST_SMEM_FLOATS 18864
#define ST_SMEM_BYTES (ST_SMEM_FLOATS * 4)

__global__ __launch_bounds__(512, 3) void st_kernel(
    const float* __restrict__ xt, const float* __restrict__ w,
    const float* __restrict__ cb, const float* __restrict__ gc1,
    const float* __restrict__ gc2, const float* __restrict__ conf,
    const float* __restrict__ gl, float* __restrict__ fin,
    float* __restrict__ gacc, int t)
{
    extern __shared__ float sm[];
    float* sf  = sm;            // 2430 (later gc1/gc2)
    float* sU  = sm + 2432;     // 13504 union region
    float* sG  = sm + 15936;    // 2704
    float* sd  = sm + 18640;    // 90
    float* scb = sm + 18736;    // 90
    float* sgl = sm + 18832;    // 27

    float* adj = sU;            // 8100
    float* sA  = sU + 8100;     // 2700
    float* sB  = sU + 10800;    // 2700

    int b = blockIdx.x, tid = threadIdx.x;
    const int NT = 512;
    const float* src = xt + (size_t)b * TNF + (size_t)t * NF;
    for (int i = tid; i < NF; i += NT) sf[i] = src[i];
    if (tid < 90) scb[tid] = cb[tid];
    else if (tid >= 128 && tid < 155) sgl[tid - 128] = gl[tid - 128];
    __syncthreads();

    // row means (needed for uncentered-cov correction; sd holds means for now)
    if (tid < 90) {
        float s = 0.f;
        #pragma unroll
        for (int f = 0; f < FD; f++) s += sf[tid * FD + f];
        sd[tid] = s * (1.f / (float)FD);
    }

    // ---- conv1: l = conv1x3(f) + cb + gl, in 2 weight-half passes ----
    #pragma unroll 1
    for (int pass = 0; pass < 2; pass++) {
        int row0 = pass * 46;
        int nrows = pass ? 44 : 46;
        int wcount = nrows * 270;
        __syncthreads();  // prior users of sU / prior pass consumers done
        for (int i = tid; i < wcount; i += NT) sU[i] = w[row0 * 270 + i];
        __syncthreads();
        for (int g = tid; g < nrows * 3; g += NT) {
            int r = g / 3, x0 = (g % 3) * 9;
            float acc[9];
            #pragma unroll
            for (int xi = 0; xi < 9; xi++) acc[xi] = 0.f;
            const float* wr = sU + r * 270;
            for (int i = 0; i < 90; i++) {
                float fv[11];
                #pragma unroll
                for (int q = 0; q < 11; q++) {
                    int xx = x0 - 1 + q;
                    fv[q] = (xx >= 0 && xx < FD) ? sf[i * FD + xx] : 0.f;
                }
                float w0 = wr[i * 3], w1 = wr[i * 3 + 1], w2 = wr[i * 3 + 2];
                #pragma unroll
                for (int xi = 0; xi < 9; xi++)
                    acc[xi] += w0 * fv[xi] + w1 * fv[xi + 1] + w2 * fv[xi + 2];
            }
            int n = row0 + r;
            #pragma unroll
            for (int xi = 0; xi < 9; xi++)
                sG[n * FD + x0 + xi] = acc[xi] + scb[n] + sgl[x0 + xi];
        }
    }
    __syncthreads();

    // ---- cov (uncentered + correction) -> adj region (w halves dead) ----
    for (int g = tid; g < 900; g += NT) {
        int n0 = (g / 30) * 3, m0 = (g % 30) * 3;
        float acc[3][3];
        #pragma unroll
        for (int r = 0; r < 3; r++)
            #pragma unroll
            for (int c = 0; c < 3; c++) acc[r][c] = 0.f;
        for (int f = 0; f < FD; f++) {
            float a0 = sf[n0 * FD + f], a1 = sf[(n0 + 1) * FD + f], a2 = sf[(n0 + 2) * FD + f];
            float c0 = sf[m0 * FD + f], c1 = sf[(m0 + 1) * FD + f], c2 = sf[(m0 + 2) * FD + f];
            acc[0][0] += a0 * c0; acc[0][1] += a0 * c1; acc[0][2] += a0 * c2;
            acc[1][0] += a1 * c0; acc[1][1] += a1 * c1; acc[1][2] += a1 * c2;
            acc[2][0] += a2 * c0; acc[2][1] += a2 * c1; acc[2][2] += a2 * c2;
        }
        #pragma unroll
        for (int r = 0; r < 3; r++) {
            float mu_n = sd[n0 + r] * (float)FD;
            #pragma unroll
            for (int c = 0; c < 3; c++)
                adj[(n0 + r) * 90 + m0 + c] = acc[r][c] - mu_n * sd[m0 + c];
        }
    }
    __syncthreads();

    // diag rsqrt (overwrite sd); load gc1/gc2 into sf region (sf dead)
    if (tid < 90) sd[tid] = rsqrtf(adj[tid * 91]);
    for (int i = tid; i < 810; i += NT) sf[i] = gc1[i];
    for (int i = tid; i < 900; i += NT) sf[810 + i] = gc2[i];
    __syncthreads();
    for (int i = tid; i < 8100; i += NT) adj[i] *= sd[i / 90] * sd[i % 90];
    __syncthreads();

    // ---- GCN chain ----
    mm_30<27, 27>(sG, sf, sA, tid, NT);        // t1 = l @ gc1
    __syncthreads();
    mm_30<90, 90>(adj, sA, sB, tid, NT);       // s1 = adj @ t1
    __syncthreads();
    mm_30<30, 30>(sB, sf + 810, sA, tid, NT);  // t2 = s1 @ gc2
    __syncthreads();
    mm_30<90, 90>(adj, sA, sG, tid, NT);       // g_out = adj @ t2 -> sG (stride 30)
    __syncthreads();

    // global column sums of g_out
    if (tid < 30) {
        float s = 0.f;
        for (int n = 0; n < 90; n++) s += sG[n * 30 + tid];
        atomicAdd(&gacc[tid], s);
    }

    float cf = conf[b * TT + t];
    // ---- conv2 on g_out (L=30), 2 weight-half passes, fused conf-weighted accumulate ----
    #pragma unroll 1
    for (int pass = 0; pass < 2; pass++) {
        int row0 = pass * 46;
        int nrows = pass ? 44 : 46;
        int wcount = nrows * 270;
        __syncthreads();  // adj/sA/sB consumers (and colsum issue) done before overwrite
        for (int i = tid; i < wcount; i += NT) sU[i] = w[row0 * 270 + i];
        __syncthreads();
        for (int g = tid; g < nrows * 3; g += NT) {
            int r = g / 3, x0 = (g % 3) * 10;
            float acc[10];
            #pragma unroll
            for (int xi = 0; xi < 10; xi++) acc[xi] = 0.f;
            const float* wr = sU + r * 270;
            for (int i = 0; i < 90; i++) {
                float fv[12];
                #pragma unroll
                for (int q = 0; q < 12; q++) {
                    int xx = x0 - 1 + q;
                    fv[q] = (xx >= 0 && xx < HD) ? sG[i * HD + xx] : 0.f;
                }
                float w0 = wr[i * 3], w1 = wr[i * 3 + 1], w2 = wr[i * 3 + 2];
                #pragma unroll
                for (int xi = 0; xi < 10; xi++)
                    acc[xi] += w0 * fv[xi] + w1 * fv[xi + 1] + w2 * fv[xi + 2];
            }
            int n = row0 + r;
            #pragma unroll
            for (int xi = 0; xi < 10; xi++) {
                int idx = b * NH + n * HD + x0 + xi;
                float val = (acc[xi] + scb[n]) * cf;
                if (t == 0) fin[idx] = val;
                else        fin[idx] += val;
            }
        }
    }
}

// ---------------- head GEMM: C[M,N] = (A*bnA+bnB)[M,K] @ W[N,K]^T + bias ----------------
__global__ __launch_bounds__(256) void gemm_kernel(
    const float* __restrict__ A, const float* __restrict__ W,
    const float* __restrict__ bias, const float* __restrict__ bnA,
    const float* __restrict__ bnB, float* __restrict__ C,
    int M, int N, int K)
{
    __shared__ float As[16][68];
    __shared__ float Ws[16][68];
    int m0 = blockIdx.y * 64, n0 = blockIdx.x * 64;
    int tid = threadIdx.x;
    int lr = tid >> 2;
    int lk = (tid & 3) * 4;
    int tx = tid & 15, ty = tid >> 4;
    float acc[4][4];
    #pragma unroll
    for (int i = 0; i < 4; i++)
        #pragma unroll
        for (int j = 0; j < 4; j++) acc[i][j] = 0.f;

    int ktiles = (K + 15) / 16;
    for (int kt = 0; kt < ktiles; kt++) {
        int k0 = kt * 16;
        float4 av, wv;
        if (k0 + lk < K) {
            av = *(const float4*)(A + (size_t)(m0 + lr) * K + k0 + lk);
            if (bnA) {
                float4 sA4 = *(const float4*)(bnA + k0 + lk);
                float4 sB4 = *(const float4*)(bnB + k0 + lk);
                av.x = av.x * sA4.x + sB4.x; av.y = av.y * sA4.y + sB4.y;
                av.z = av.z * sA4.z + sB4.z; av.w = av.w * sA4.w + sB4.w;
            }
            wv = *(const float4*)(W + (size_t)(n0 + lr) * K + k0 + lk);
        } else {
            av = make_float4(0.f, 0.f, 0.f, 0.f);
            wv = make_float4(0.f, 0.f, 0.f, 0.f);
        }
        __syncthreads();
        As[lk][lr] = av.x; As[lk + 1][lr] = av.y; As[lk + 2][lr] = av.z; As[lk + 3][lr] = av.w;
        Ws[lk][lr] = wv.x; Ws[lk + 1][lr] = wv.y; Ws[lk + 2][lr] = wv.z; Ws[lk + 3][lr] = wv.w;
        __syncthreads();
        #pragma unroll
        for (int kk = 0; kk < 16; kk++) {
            float rA[4], rB[4];
            #pragma unroll
            for (int i = 0; i < 4; i++) rA[i] = As[kk][ty * 4 + i];
            #pragma unroll
            for (int j = 0; j < 4; j++) rB[j] = Ws[kk][tx * 4 + j];
            #pragma unroll
            for (int i = 0; i < 4; i++)
                #pragma unroll
                for (int j = 0; j < 4; j++) acc[i][j] += rA[i] * rB[j];
        }
    }
    #pragma unroll
    for (int i = 0; i < 4; i++) {
        int m = m0 + ty * 4 + i;
        #pragma unroll
        for (int j = 0; j < 4; j++) {
            int n = n0 + tx * 4 + j;
            C[(size_t)m * N + n] = acc[i][j] + bias[n];
        }
    }
}

// ---------------- BN stats: per-column mean/var -> affine (bnA, bnB) ----------------
__global__ void bnstats_kernel(const float* __restrict__ C,
                               const float* __restrict__ gamma, const float* __restrict__ beta,
                               float* __restrict__ bnA, float* __restrict__ bnB, int N)
{
    __shared__ double rs[8][32];
    __shared__ double rq[8][32];
    int col = blockIdx.x * 32 + threadIdx.x;
    int g = threadIdx.y;
    double s = 0.0, q = 0.0;
    for (int r = g; r < BB; r += 8) {
        double v = (double)C[(size_t)r * N + col];
        s += v; q += v * v;
    }
    rs[g][threadIdx.x] = s; rq[g][threadIdx.x] = q;
    __syncthreads();
    if (g == 0) {
        for (int k = 1; k < 8; k++) { s += rs[k][threadIdx.x]; q += rq[k][threadIdx.x]; }
        float mean = (float)(s / (double)BB);
        float var = (float)(q / (double)BB) - mean * mean;
        float a = gamma[col] * rsqrtf(var + 1e-5f);
        bnA[col] = a;
        bnB[col] = beta[col] - mean * a;
    }
}

// ---------------- final: bn2-apply + 256->2 linear + softmax ----------------
__global__ __launch_bounds__(256) void head_kernel(
    const float* __restrict__ h2, const float* __restrict__ bnA,
    const float* __restrict__ bnB, const float* __restrict__ l3w,
    const float* __restrict__ l3b, float* __restrict__ out)
{
    int gw = (blockIdx.x * blockDim.x + threadIdx.x) >> 5;
    int lane = threadIdx.x & 31;
    if (gw >= BB) return;
    const float* row = h2 + (size_t)gw * 256;
    float z0 = 0.f, z1 = 0.f;
    for (int k = lane; k < 256; k += 32) {
        float hb = row[k] * bnA[k] + bnB[k];
        z0 += hb * l3w[k];
        z1 += hb * l3w[256 + k];
    }
    #pragma unroll
    for (int off = 16; off > 0; off >>= 1) {
        z0 += __shfl_down_sync(0xffffffffu, z0, off);
        z1 += __shfl_down_sync(0xffffffffu, z1, off);
    }
    if (lane == 0) {
        z0 += l3b[0]; z1 += l3b[1];
        float m = fmaxf(z0, z1);
        float e0 = expf(z0 - m), e1 = expf(z1 - m);
        float inv = 1.f / (e0 + e1);
        out[gw * 2 + 0] = e0 * inv;
        out[gw * 2 + 1] = e1 * inv;
    }
}

// ---------------- launch ----------------
extern "C" void kernel_launch(void* const* d_in, const int* in_sizes, int n_in,
                              void* d_out, int out_size)
{
    const float* fdata = (const float*)d_in[0];
    const float* un_w  = (const float*)d_in[1];
    const float* un_b  = (const float*)d_in[2];
    const float* U1    = (const float*)d_in[3];
    const float* U2    = (const float*)d_in[4];
    const float* U3    = (const float*)d_in[5];
    const float* b_e   = (const float*)d_in[6];
    const float* v_e   = (const float*)d_in[7];
    const float* gc1_w = (const float*)d_in[8];
    const float* gc2_w = (const float*)d_in[9];
    const float* cnn1w = (const float*)d_in[10];
    const float* cnn1b = (const float*)d_in[11];
    const float* lin_w = (const float*)d_in[12];
    const float* lin_b = (const float*)d_in[13];
    const float* l1_w  = (const float*)d_in[14];
    const float* l1_b  = (const float*)d_in[15];
    const float* bn1_g = (const float*)d_in[16];
    const float* bn1_b = (const float*)d_in[17];
    const float* l2_w  = (const float*)d_in[18];
    const float* l2_b  = (const float*)d_in[19];
    const float* bn2_g = (const float*)d_in[20];
    const float* bn2_b = (const float*)d_in[21];
    const float* l3_w  = (const float*)d_in[22];
    const float* l3_b  = (const float*)d_in[23];
    float* out = (float*)d_out;

    cudaFuncSetAttribute(attn_kernel, cudaFuncAttributeMaxDynamicSharedMemorySize, ATTN_SMEM_BYTES);
    cudaFuncSetAttribute(st_kernel, cudaFuncAttributeMaxDynamicSharedMemorySize, ST_SMEM_BYTES);

    float *xt, *conf, *fin, *h1, *h2, *gacc, *gl, *bnA1, *bnB1, *bnA2, *bnB2;
    cudaGetSymbolAddress((void**)&xt, g_xt);
    cudaGetSymbolAddress((void**)&conf, g_conf);
    cudaGetSymbolAddress((void**)&fin, g_final);
    cudaGetSymbolAddress((void**)&h1, g_h1);
    cudaGetSymbolAddress((void**)&h2, g_h2);
    cudaGetSymbolAddress((void**)&gacc, g_gacc);
    cudaGetSymbolAddress((void**)&gl, g_gl);
    cudaGetSymbolAddress((void**)&bnA1, g_bnA1);
    cudaGetSymbolAddress((void**)&bnB1, g_bnB1);
    cudaGetSymbolAddress((void**)&bnA2, g_bnA2);
    cudaGetSymbolAddress((void**)&bnB2, g_bnB2);

    attn_kernel<<<BB, 256, ATTN_SMEM_BYTES>>>(fdata, U1, U2, U3, b_e, v_e, xt);
    conf_kernel<<<(BB * TT * 32 + 255) / 256, 256>>>(fdata, un_w, un_b, conf);
    init_kernel<<<1, 32>>>(lin_b, gl, gacc);
    for (int t = 0; t < TT; t++) {
        st_kernel<<<BB, 512, ST_SMEM_BYTES>>>(xt, cnn1w, cnn1b, gc1_w, gc2_w, conf, gl, fin, gacc, t);
        if (t < TT - 1)
            gl_kernel<<<1, 32>>>(lin_w, lin_b, gl, gacc);
    }
    gemm_kernel<<<dim3(1024 / 64, BB / 64), 256>>>(fin, l1_w, l1_b, nullptr, nullptr, h1, BB, 1024, NH);
    bnstats_kernel<<<1024 / 32, dim3(32, 8)>>>(h1, bn1_g, bn1_b, bnA1, bnB1, 1024);
    gemm_kernel<<<dim3(256 / 64, BB / 64), 256>>>(h1, l2_w, l2_b, bnA1, bnB1, h2, BB, 256, 1024);
    bnstats_kernel<<<256 / 32, dim3(32, 8)>>>(h2, bn2_g, bn2_b, bnA2, bnB2, 256);
    head_kernel<<<(BB * 32 + 255) / 256, 256>>>(h2, bnA2, bnB2, l3_w, l3_b, out);
}